// round 7
// baseline (speedup 1.0000x reference)
#include <cuda_runtime.h>
#include <cuda_fp16.h>
#include <cstdint>
#include <cstddef>

// ---------------------------------------------------------------------------
// Problem constants
// ---------------------------------------------------------------------------
#define TOKENS 4096   // M
#define IN_F   4096   // K
#define OUT_F  11008  // N

// GEMM tiling: CTA 128x128, 8 warps (2m x 4n), warp tile m64n32, 2 CTAs/SM.
// A via cp.async+ldmatrix (R2 machinery). B expanded from 2-bit planes in regs.
#define BM 128
#define BN 128
#define BK 32
#define KTILES (IN_F / BK)   // 128
#define STAGES 4
#define KWORDS (IN_F / 32)   // uint2 words per row of packed q

#define A_STAGE_BYTES (BM * BK * 2)          // 8192
#define STAGE_BYTES   A_STAGE_BYTES
#define SMEM_TOTAL    (STAGES * STAGE_BYTES) // 32768

// ---------------------------------------------------------------------------
// Device scratch (static — no cudaMalloc anywhere)
// ---------------------------------------------------------------------------
__device__ uint2   g_qp[(size_t)OUT_F * KWORDS];  // packed ternary: .x=nonzero bits, .y=sign bits
__device__ __half  g_xh[(size_t)TOKENS * IN_F];   // fp16(x)
__device__ double  g_partial[1024];
__device__ float   g_alpha;

// ---------------------------------------------------------------------------
// PTX helpers (baseline compute_103 — NO tcgen05/TMA-arch features)
// ---------------------------------------------------------------------------
__device__ __forceinline__ uint32_t smem_u32(const void* p) {
    uint32_t a;
    asm("{ .reg .u64 t; cvta.to.shared.u64 t, %1; cvt.u32.u64 %0, t; }"
        : "=r"(a) : "l"(p));
    return a;
}

__device__ __forceinline__ void cp_async16(uint32_t s, const void* g) {
    asm volatile(
        "{ .reg .u64 gg; cvta.to.global.u64 gg, %1; "
        "cp.async.cg.shared.global [%0], [gg], 16; }"
        :: "r"(s), "l"(g));
}
#define CP_COMMIT() asm volatile("cp.async.commit_group;" ::: "memory")
#define CP_WAIT(N)  asm volatile("cp.async.wait_group %0;" :: "n"(N) : "memory")

__device__ __forceinline__ void ldsm_x4(uint32_t& r0, uint32_t& r1,
                                        uint32_t& r2, uint32_t& r3, uint32_t a) {
    asm volatile("ldmatrix.sync.aligned.m8n8.x4.shared.b16 {%0,%1,%2,%3}, [%4];"
                 : "=r"(r0), "=r"(r1), "=r"(r2), "=r"(r3) : "r"(a));
}

__device__ __forceinline__ void mma16816(float& c0, float& c1, float& c2, float& c3,
                                         uint32_t a0, uint32_t a1, uint32_t a2, uint32_t a3,
                                         uint32_t b0, uint32_t b1) {
    asm volatile(
        "mma.sync.aligned.m16n8k16.row.col.f32.f16.f16.f32 "
        "{%0,%1,%2,%3}, {%4,%5,%6,%7}, {%8,%9}, {%0,%1,%2,%3};"
        : "+f"(c0), "+f"(c1), "+f"(c2), "+f"(c3)
        : "r"(a0), "r"(a1), "r"(a2), "r"(a3), "r"(b0), "r"(b1));
}

// 16B-chunk swizzle for 64B rows (A tile): chunk cc (0..3), row r.
__device__ __forceinline__ uint32_t swz(uint32_t row, uint32_t cc) {
    return row * 64u + ((cc ^ ((row >> 1) & 3u)) << 4);
}

// Expand two consecutive 2-bit ternary weights (bits c, c+1 of pre-shifted
// planes) into one packed fp16x2 register. fp16(+1)=0x3C00, fp16(-1)=0xBC00.
__device__ __forceinline__ uint32_t expand_pair(uint32_t nzs, uint32_t sgs, int c) {
    uint32_t r = ((nzs >> c) & 1u) * 0x3C00u;
    r |= ((sgs >> c) & 1u) << 15;
    r |= (((nzs >> (c + 1)) & 1u) * 0x3C00u) << 16;
    r |= ((sgs >> (c + 1)) & 1u) << 31;
    return r;
}

// ---------------------------------------------------------------------------
// Kernel 1: deterministic |W| partial sums (fp64 accumulators)
// ---------------------------------------------------------------------------
__global__ void reduce_abs_kernel(const float* __restrict__ w) {
    __shared__ double sh[256];
    const size_t n4 = (size_t)OUT_F * IN_F / 4;
    const float4* w4 = (const float4*)w;
    double acc = 0.0;
    for (size_t i = (size_t)blockIdx.x * 256 + threadIdx.x; i < n4;
         i += (size_t)1024 * 256) {
        float4 v = w4[i];
        acc += (double)fabsf(v.x) + (double)fabsf(v.y) +
               (double)fabsf(v.z) + (double)fabsf(v.w);
    }
    int tid = threadIdx.x;
    sh[tid] = acc;
    __syncthreads();
    for (int s = 128; s > 0; s >>= 1) {
        if (tid < s) sh[tid] += sh[tid + s];
        __syncthreads();
    }
    if (tid == 0) g_partial[blockIdx.x] = sh[0];
}

__global__ void finalize_alpha_kernel() {
    __shared__ double sh[256];
    int tid = threadIdx.x;
    double a = g_partial[tid] + g_partial[tid + 256] +
               g_partial[tid + 512] + g_partial[tid + 768];
    sh[tid] = a;
    __syncthreads();
    for (int s = 128; s > 0; s >>= 1) {
        if (tid < s) sh[tid] += sh[tid + s];
        __syncthreads();
    }
    if (tid == 0) g_alpha = (float)(sh[0] / ((double)OUT_F * (double)IN_F));
}

// ---------------------------------------------------------------------------
// Kernel 3: ternary quantize + 2-bit bitplane pack (ballot). One thread per
// weight; each warp covers 32 consecutive k of one row -> one uint2 word.
// ---------------------------------------------------------------------------
__global__ void quantize_pack_kernel(const float* __restrict__ w) {
    const float a = g_alpha;
    size_t idx = (size_t)blockIdx.x * blockDim.x + threadIdx.x;
    float v = w[idx];
    bool neg = (v < -a);
    bool nz = (v > a) || neg;
    uint32_t nzm = __ballot_sync(0xFFFFFFFFu, nz);
    uint32_t sgm = __ballot_sync(0xFFFFFFFFu, neg);
    if ((threadIdx.x & 31) == 0)
        g_qp[idx >> 5] = make_uint2(nzm, sgm);
}

// ---------------------------------------------------------------------------
// Kernel 4: x -> fp16
// ---------------------------------------------------------------------------
__global__ void convert_x_kernel(const float* __restrict__ x) {
    size_t i = (size_t)blockIdx.x * blockDim.x + threadIdx.x;
    const size_t n4 = (size_t)TOKENS * IN_F / 4;
    if (i >= n4) return;
    float4 v = ((const float4*)x)[i];
    __half2* o = (__half2*)g_xh;
    o[i * 2 + 0] = __half2(__float2half_rn(v.x), __float2half_rn(v.y));
    o[i * 2 + 1] = __half2(__float2half_rn(v.z), __float2half_rn(v.w));
}

// ---------------------------------------------------------------------------
// Kernel 5: fp16 HMMA GEMM. A: cp.async->smem->ldmatrix (R2 path).
// B: 2-bit planes LDG'd per kt (double-buffered) and expanded to fp16
// fragments in registers — zero smem traffic for B.
// out[m, n] = (sum_k xh[m,k] * q[n,k]) * scale[n] + bias[n]
// ---------------------------------------------------------------------------
__device__ __forceinline__ void load_stage_A(uint32_t sbase, int k0,
                                             const __half* __restrict__ xrow,
                                             int tid) {
    // A: 128 rows x 32 halves = 512 16B chunks; 2 cp.async per thread.
#pragma unroll
    for (int j = 0; j < 2; j++) {
        int id = tid + j * 256;
        uint32_t row = (uint32_t)(id >> 2);
        uint32_t cc = (uint32_t)(id & 3);
        cp_async16(sbase + swz(row, cc),
                   xrow + (size_t)row * IN_F + k0 + cc * 8);
    }
}

__global__ void __launch_bounds__(256, 2)
gemm_kernel(float* __restrict__ out, const float* __restrict__ scale,
            const float* __restrict__ bias) {
    extern __shared__ char smem[];
    const uint32_t sb = smem_u32(smem);
    const int tid = threadIdx.x;
    const int lane = tid & 31;
    const int wid = tid >> 5;
    const int warp_m = (wid & 1) * 64;
    const int warp_n = (wid >> 1) * 32;

    const int m0 = blockIdx.x * BM;   // m fastest -> packed q tile L2-shared
    const int n0 = blockIdx.y * BN;

    const __half* xrow = g_xh + (size_t)m0 * IN_F;
    // Packed-q pointer for this thread's base n row (nt adds 8 rows each).
    const uint2* qp = g_qp + (size_t)(n0 + warp_n + (lane >> 2)) * KWORDS;
    const int bp = (lane & 3) * 2;   // bit shift within 32-k word

    // ldmatrix swizzled A offsets (ks folds in as XOR with ks<<5).
    uint32_t offA[4];
#pragma unroll
    for (int mt = 0; mt < 4; mt++)
        offA[mt] = swz((uint32_t)(warp_m + mt * 16 + (lane & 15)),
                       (uint32_t)(lane >> 4));

    float acc[4][4][4];
#pragma unroll
    for (int mt = 0; mt < 4; mt++)
#pragma unroll
        for (int nt = 0; nt < 4; nt++)
#pragma unroll
            for (int j = 0; j < 4; j++) acc[mt][nt][j] = 0.0f;

    // Prologue: A stages 0..2, B words for kt=0.
#pragma unroll
    for (int s = 0; s < STAGES - 1; s++) {
        load_stage_A(sb + s * STAGE_BYTES, s * BK, xrow, tid);
        CP_COMMIT();
    }
    uint2 bw[4];
#pragma unroll
    for (int nt = 0; nt < 4; nt++) bw[nt] = __ldg(qp + nt * 8 * KWORDS);

    int s_comp = 0, s_load = STAGES - 1;
    for (int kt = 0; kt < KTILES; kt++) {
        CP_WAIT(STAGES - 2);
        __syncthreads();

        int kn = kt + STAGES - 1;
        if (kn < KTILES)
            load_stage_A(sb + s_load * STAGE_BYTES, kn * BK, xrow, tid);
        CP_COMMIT();
        if (++s_load == STAGES) s_load = 0;

        // Prefetch next kt's packed-B words (L2-resident, 1 iteration ahead).
        uint2 bwn[4];
        const int ktn = (kt + 1 < KTILES) ? kt + 1 : kt;
#pragma unroll
        for (int nt = 0; nt < 4; nt++)
            bwn[nt] = __ldg(qp + nt * 8 * KWORDS + ktn);

        const uint32_t stage = sb + s_comp * STAGE_BYTES;
        if (++s_comp == STAGES) s_comp = 0;

#pragma unroll
        for (int ks = 0; ks < 2; ks++) {
            const uint32_t kx = (uint32_t)(ks << 5);
            uint32_t af[4][4];
#pragma unroll
            for (int mt = 0; mt < 4; mt++)
                ldsm_x4(af[mt][0], af[mt][1], af[mt][2], af[mt][3],
                        stage + (offA[mt] ^ kx));
            // Expand B fragments from bitplanes: k = ks*16 + bp + {0,1} (+8).
            uint32_t bf[4][2];
#pragma unroll
            for (int nt = 0; nt < 4; nt++) {
                const uint32_t nzs = bw[nt].x >> bp;
                const uint32_t sgs = bw[nt].y >> bp;
                bf[nt][0] = expand_pair(nzs, sgs, ks * 16);
                bf[nt][1] = expand_pair(nzs, sgs, ks * 16 + 8);
            }
#pragma unroll
            for (int mt = 0; mt < 4; mt++)
#pragma unroll
                for (int nt = 0; nt < 4; nt++)
                    mma16816(acc[mt][nt][0], acc[mt][nt][1],
                             acc[mt][nt][2], acc[mt][nt][3],
                             af[mt][0], af[mt][1], af[mt][2], af[mt][3],
                             bf[nt][0], bf[nt][1]);
        }

#pragma unroll
        for (int nt = 0; nt < 4; nt++) bw[nt] = bwn[nt];
    }

    // Epilogue: scale + bias, direct fp32 stores.
#pragma unroll
    for (int nt = 0; nt < 4; nt++) {
        const int c = n0 + warp_n + nt * 8 + (lane & 3) * 2;
        const float s0 = __ldg(scale + c), s1 = __ldg(scale + c + 1);
        const float b0 = __ldg(bias + c), b1 = __ldg(bias + c + 1);
#pragma unroll
        for (int mt = 0; mt < 4; mt++) {
            const int r0 = m0 + warp_m + mt * 16 + (lane >> 2);
            float2 v0 = {acc[mt][nt][0] * s0 + b0, acc[mt][nt][1] * s1 + b1};
            float2 v1 = {acc[mt][nt][2] * s0 + b0, acc[mt][nt][3] * s1 + b1};
            *(float2*)(out + (size_t)r0 * OUT_F + c) = v0;
            *(float2*)(out + (size_t)(r0 + 8) * OUT_F + c) = v1;
        }
    }
}

// ---------------------------------------------------------------------------
// kernel_launch
// ---------------------------------------------------------------------------
extern "C" void kernel_launch(void* const* d_in, const int* in_sizes, int n_in,
                              void* d_out, int out_size) {
    const float* x      = (const float*)d_in[0];  // (4096, 4096)
    const float* weight = (const float*)d_in[1];  // (11008, 4096)
    const float* scale  = (const float*)d_in[2];  // (11008, 1)
    const float* bias   = (const float*)d_in[3];  // (11008,)
    float* out = (float*)d_out;                   // (4096, 11008)
    (void)in_sizes; (void)n_in; (void)out_size;

    reduce_abs_kernel<<<1024, 256>>>(weight);
    finalize_alpha_kernel<<<1, 256>>>();
    quantize_pack_kernel<<<(int)(((size_t)OUT_F * IN_F) / 256), 256>>>(weight);
    convert_x_kernel<<<(int)(((size_t)TOKENS * IN_F / 4 + 255) / 256), 256>>>(x);

    cudaFuncSetAttribute(gemm_kernel,
                         cudaFuncAttributeMaxDynamicSharedMemorySize, SMEM_TOTAL);
    dim3 grid(TOKENS / BM, OUT_F / BN);  // (32, 86)
    gemm_kernel<<<grid, 256, SMEM_TOTAL>>>(out, scale, bias);
}

// round 9
// speedup vs baseline: 1.1269x; 1.1269x over previous
#include <cuda_runtime.h>
#include <cuda_fp16.h>
#include <cstdint>
#include <cstddef>

// ---------------------------------------------------------------------------
// Problem constants
// ---------------------------------------------------------------------------
#define TOKENS 4096   // M
#define IN_F   4096   // K
#define OUT_F  11008  // N

// GEMM tiling: CTA 128x128, 8 warps (2m x 4n), warp tile m64n32, 2 CTAs/SM.
// Exact R2 structure; only change: f16 accumulators chained over one kt
// (k=32), promoted to f32 once per kt.
#define BM 128
#define BN 128
#define BK 32
#define KTILES (IN_F / BK)   // 128
#define STAGES 4

#define A_STAGE_BYTES (BM * BK * 2)          // 8192
#define B_STAGE_BYTES (BN * BK * 2)          // 8192
#define STAGE_BYTES   (A_STAGE_BYTES + B_STAGE_BYTES)   // 16384
#define SMEM_TOTAL    (STAGES * STAGE_BYTES)            // 65536

// ---------------------------------------------------------------------------
// Device scratch (static — no cudaMalloc anywhere)
// ---------------------------------------------------------------------------
__device__ __half  g_q[(size_t)OUT_F * IN_F];    // ternary weights, fp16 exact
__device__ __half  g_xh[(size_t)TOKENS * IN_F];  // fp16(x)
__device__ double  g_partial[1024];
__device__ float   g_alpha;

// ---------------------------------------------------------------------------
// PTX helpers (baseline compute_103 — NO tcgen05/TMA-arch features)
// ---------------------------------------------------------------------------
__device__ __forceinline__ uint32_t smem_u32(const void* p) {
    uint32_t a;
    asm("{ .reg .u64 t; cvta.to.shared.u64 t, %1; cvt.u32.u64 %0, t; }"
        : "=r"(a) : "l"(p));
    return a;
}

__device__ __forceinline__ void cp_async16(uint32_t s, const void* g) {
    asm volatile(
        "{ .reg .u64 gg; cvta.to.global.u64 gg, %1; "
        "cp.async.cg.shared.global [%0], [gg], 16; }"
        :: "r"(s), "l"(g));
}
#define CP_COMMIT() asm volatile("cp.async.commit_group;" ::: "memory")
#define CP_WAIT(N)  asm volatile("cp.async.wait_group %0;" :: "n"(N) : "memory")

__device__ __forceinline__ void ldsm_x4(uint32_t& r0, uint32_t& r1,
                                        uint32_t& r2, uint32_t& r3, uint32_t a) {
    asm volatile("ldmatrix.sync.aligned.m8n8.x4.shared.b16 {%0,%1,%2,%3}, [%4];"
                 : "=r"(r0), "=r"(r1), "=r"(r2), "=r"(r3) : "r"(a));
}

// f16-accumulator MMA: D(f16x2 x2) = A(f16) * B(f16) + C(f16x2 x2). 2x rate
// vs f32 accum on the legacy tensor path.
__device__ __forceinline__ void mma16816_h(uint32_t& d0, uint32_t& d1,
                                           uint32_t a0, uint32_t a1, uint32_t a2, uint32_t a3,
                                           uint32_t b0, uint32_t b1) {
    asm volatile(
        "mma.sync.aligned.m16n8k16.row.col.f16.f16.f16.f16 "
        "{%0,%1}, {%2,%3,%4,%5}, {%6,%7}, {%0,%1};"
        : "+r"(d0), "+r"(d1)
        : "r"(a0), "r"(a1), "r"(a2), "r"(a3), "r"(b0), "r"(b1));
}

// 16B-chunk swizzle for 64B rows: chunk col cc (0..3), row r.
// Conflict-free for ldmatrix phases AND cp.async writes.
__device__ __forceinline__ uint32_t swz(uint32_t row, uint32_t cc) {
    return row * 64u + ((cc ^ ((row >> 1) & 3u)) << 4);
}

// ---------------------------------------------------------------------------
// Kernel 1: deterministic |W| partial sums (fp64 accumulators)
// ---------------------------------------------------------------------------
__global__ void reduce_abs_kernel(const float* __restrict__ w) {
    __shared__ double sh[256];
    const size_t n4 = (size_t)OUT_F * IN_F / 4;
    const float4* w4 = (const float4*)w;
    double acc = 0.0;
    for (size_t i = (size_t)blockIdx.x * 256 + threadIdx.x; i < n4;
         i += (size_t)1024 * 256) {
        float4 v = w4[i];
        acc += (double)fabsf(v.x) + (double)fabsf(v.y) +
               (double)fabsf(v.z) + (double)fabsf(v.w);
    }
    int tid = threadIdx.x;
    sh[tid] = acc;
    __syncthreads();
    for (int s = 128; s > 0; s >>= 1) {
        if (tid < s) sh[tid] += sh[tid + s];
        __syncthreads();
    }
    if (tid == 0) g_partial[blockIdx.x] = sh[0];
}

__global__ void finalize_alpha_kernel() {
    __shared__ double sh[256];
    int tid = threadIdx.x;
    double a = g_partial[tid] + g_partial[tid + 256] +
               g_partial[tid + 512] + g_partial[tid + 768];
    sh[tid] = a;
    __syncthreads();
    for (int s = 128; s > 0; s >>= 1) {
        if (tid < s) sh[tid] += sh[tid + s];
        __syncthreads();
    }
    if (tid == 0) g_alpha = (float)(sh[0] / ((double)OUT_F * (double)IN_F));
}

// ---------------------------------------------------------------------------
// Kernel 3: ternary quantize W -> fp16 {-1, 0, +1}
// ---------------------------------------------------------------------------
__global__ void quantize_kernel(const float* __restrict__ w) {
    const float a = g_alpha;
    size_t i = (size_t)blockIdx.x * blockDim.x + threadIdx.x;
    const size_t n4 = (size_t)OUT_F * IN_F / 4;
    if (i >= n4) return;
    float4 v = ((const float4*)w)[i];
    float q0 = (v.x > a) ? 1.0f : ((v.x < -a) ? -1.0f : 0.0f);
    float q1 = (v.y > a) ? 1.0f : ((v.y < -a) ? -1.0f : 0.0f);
    float q2 = (v.z > a) ? 1.0f : ((v.z < -a) ? -1.0f : 0.0f);
    float q3 = (v.w > a) ? 1.0f : ((v.w < -a) ? -1.0f : 0.0f);
    __half2* o = (__half2*)g_q;
    o[i * 2 + 0] = __half2(__float2half_rn(q0), __float2half_rn(q1));
    o[i * 2 + 1] = __half2(__float2half_rn(q2), __float2half_rn(q3));
}

// ---------------------------------------------------------------------------
// Kernel 4: x -> fp16
// ---------------------------------------------------------------------------
__global__ void convert_x_kernel(const float* __restrict__ x) {
    size_t i = (size_t)blockIdx.x * blockDim.x + threadIdx.x;
    const size_t n4 = (size_t)TOKENS * IN_F / 4;
    if (i >= n4) return;
    float4 v = ((const float4*)x)[i];
    __half2* o = (__half2*)g_xh;
    o[i * 2 + 0] = __half2(__float2half_rn(v.x), __float2half_rn(v.y));
    o[i * 2 + 1] = __half2(__float2half_rn(v.z), __float2half_rn(v.w));
}

// ---------------------------------------------------------------------------
// Kernel 5: fp16 HMMA GEMM (R2 structure). f16 accum chained over one kt
// (2 MMAs, k=32), promoted to f32 each kt.
// out[m, n] = (sum_k xh[m,k] * q[n,k]) * scale[n] + bias[n]
// ---------------------------------------------------------------------------
__device__ __forceinline__ void load_stage(uint32_t sbase, int k0,
                                           const __half* __restrict__ xrow,
                                           const __half* __restrict__ qrow,
                                           int tid) {
    // A: 128 rows x 32 halves = 512 16B chunks; B: same.
#pragma unroll
    for (int j = 0; j < 2; j++) {
        int id = tid + j * 256;
        uint32_t row = (uint32_t)(id >> 2);
        uint32_t cc = (uint32_t)(id & 3);
        cp_async16(sbase + swz(row, cc),
                   xrow + (size_t)row * IN_F + k0 + cc * 8);
        cp_async16(sbase + A_STAGE_BYTES + swz(row, cc),
                   qrow + (size_t)row * IN_F + k0 + cc * 8);
    }
}

__global__ void __launch_bounds__(256, 2)
gemm_kernel(float* __restrict__ out, const float* __restrict__ scale,
            const float* __restrict__ bias) {
    extern __shared__ char smem[];
    const uint32_t sb = smem_u32(smem);
    const int tid = threadIdx.x;
    const int lane = tid & 31;
    const int wid = tid >> 5;
    const int warp_m = (wid & 1) * 64;
    const int warp_n = (wid >> 1) * 32;

    const int m0 = blockIdx.x * BM;   // m fastest -> q n-tiles L2-shared
    const int n0 = blockIdx.y * BN;

    const __half* xrow = g_xh + (size_t)m0 * IN_F;
    const __half* qrow = g_q + (size_t)n0 * IN_F;

    // Precompute ldmatrix swizzled offsets (relative to stage base).
    uint32_t offA[4][2], offB[2][2];
#pragma unroll
    for (int mt = 0; mt < 4; mt++) {
        uint32_t row = (uint32_t)(warp_m + mt * 16 + (lane & 15));
        uint32_t c0 = (uint32_t)(lane >> 4);
#pragma unroll
        for (int ks = 0; ks < 2; ks++)
            offA[mt][ks] = swz(row, (uint32_t)(ks * 2) + c0);
    }
#pragma unroll
    for (int ng = 0; ng < 2; ng++) {
        uint32_t row = (uint32_t)(warp_n + ng * 16 + ((lane >> 4) << 3) + (lane & 7));
        uint32_t c0 = (uint32_t)((lane >> 3) & 1);
#pragma unroll
        for (int ks = 0; ks < 2; ks++)
            offB[ng][ks] = A_STAGE_BYTES + swz(row, (uint32_t)(ks * 2) + c0);
    }

    float acc[4][4][4];
#pragma unroll
    for (int mt = 0; mt < 4; mt++)
#pragma unroll
        for (int nt = 0; nt < 4; nt++)
#pragma unroll
            for (int j = 0; j < 4; j++) acc[mt][nt][j] = 0.0f;

    // Prologue: stages 0..2
#pragma unroll
    for (int s = 0; s < STAGES - 1; s++) {
        load_stage(sb + s * STAGE_BYTES, s * BK, xrow, qrow, tid);
        CP_COMMIT();
    }

    for (int kt = 0; kt < KTILES; kt++) {
        CP_WAIT(STAGES - 2);
        __syncthreads();

        int kn = kt + STAGES - 1;
        if (kn < KTILES)
            load_stage(sb + (kn & (STAGES - 1)) * STAGE_BYTES, kn * BK,
                       xrow, qrow, tid);
        CP_COMMIT();

        const uint32_t stage = sb + (kt & (STAGES - 1)) * STAGE_BYTES;

        // f16 chain accumulators for this kt (zeroed).
        uint32_t hacc[4][4][2];
#pragma unroll
        for (int mt = 0; mt < 4; mt++)
#pragma unroll
            for (int nt = 0; nt < 4; nt++) {
                hacc[mt][nt][0] = 0u; hacc[mt][nt][1] = 0u;
            }

#pragma unroll
        for (int ks = 0; ks < 2; ks++) {
            uint32_t af[4][4];
            uint32_t bf[4][2];
#pragma unroll
            for (int mt = 0; mt < 4; mt++)
                ldsm_x4(af[mt][0], af[mt][1], af[mt][2], af[mt][3],
                        stage + offA[mt][ks]);
#pragma unroll
            for (int ng = 0; ng < 2; ng++) {
                uint32_t r0, r1, r2, r3;
                ldsm_x4(r0, r1, r2, r3, stage + offB[ng][ks]);
                bf[2 * ng + 0][0] = r0; bf[2 * ng + 0][1] = r1;
                bf[2 * ng + 1][0] = r2; bf[2 * ng + 1][1] = r3;
            }
#pragma unroll
            for (int mt = 0; mt < 4; mt++)
#pragma unroll
                for (int nt = 0; nt < 4; nt++)
                    mma16816_h(hacc[mt][nt][0], hacc[mt][nt][1],
                               af[mt][0], af[mt][1], af[mt][2], af[mt][3],
                               bf[nt][0], bf[nt][1]);
        }

        // Promote f16 chain into f32 accumulators.
#pragma unroll
        for (int mt = 0; mt < 4; mt++)
#pragma unroll
            for (int nt = 0; nt < 4; nt++) {
                float2 lo = __half22float2(*(const __half2*)&hacc[mt][nt][0]);
                float2 hi = __half22float2(*(const __half2*)&hacc[mt][nt][1]);
                acc[mt][nt][0] += lo.x;
                acc[mt][nt][1] += lo.y;
                acc[mt][nt][2] += hi.x;
                acc[mt][nt][3] += hi.y;
            }
    }

    // Epilogue: scale + bias, direct fp32 stores.
#pragma unroll
    for (int nt = 0; nt < 4; nt++) {
        const int c = n0 + warp_n + nt * 8 + (lane & 3) * 2;
        const float s0 = __ldg(scale + c), s1 = __ldg(scale + c + 1);
        const float b0 = __ldg(bias + c), b1 = __ldg(bias + c + 1);
#pragma unroll
        for (int mt = 0; mt < 4; mt++) {
            const int r0 = m0 + warp_m + mt * 16 + (lane >> 2);
            float2 v0 = {acc[mt][nt][0] * s0 + b0, acc[mt][nt][1] * s1 + b1};
            float2 v1 = {acc[mt][nt][2] * s0 + b0, acc[mt][nt][3] * s1 + b1};
            *(float2*)(out + (size_t)r0 * OUT_F + c) = v0;
            *(float2*)(out + (size_t)(r0 + 8) * OUT_F + c) = v1;
        }
    }
}

// ---------------------------------------------------------------------------
// kernel_launch
// ---------------------------------------------------------------------------
extern "C" void kernel_launch(void* const* d_in, const int* in_sizes, int n_in,
                              void* d_out, int out_size) {
    const float* x      = (const float*)d_in[0];  // (4096, 4096)
    const float* weight = (const float*)d_in[1];  // (11008, 4096)
    const float* scale  = (const float*)d_in[2];  // (11008, 1)
    const float* bias   = (const float*)d_in[3];  // (11008,)
    float* out = (float*)d_out;                   // (4096, 11008)
    (void)in_sizes; (void)n_in; (void)out_size;

    reduce_abs_kernel<<<1024, 256>>>(weight);
    finalize_alpha_kernel<<<1, 256>>>();
    quantize_kernel<<<(int)(((size_t)OUT_F * IN_F / 4 + 255) / 256), 256>>>(weight);
    convert_x_kernel<<<(int)(((size_t)TOKENS * IN_F / 4 + 255) / 256), 256>>>(x);

    cudaFuncSetAttribute(gemm_kernel,
                         cudaFuncAttributeMaxDynamicSharedMemorySize, SMEM_TOTAL);
    dim3 grid(TOKENS / BM, OUT_F / BN);  // (32, 86)
    gemm_kernel<<<grid, 256, SMEM_TOTAL>>>(out, scale, bias);
}

// round 10
// speedup vs baseline: 1.4550x; 1.2911x over previous
#include <cuda_runtime.h>
#include <cuda_fp16.h>
#include <cstdint>
#include <cstddef>

// ---------------------------------------------------------------------------
// Problem constants
// ---------------------------------------------------------------------------
#define TOKENS 4096   // M
#define IN_F   4096   // K
#define OUT_F  11008  // N

// GEMM tiling: CTA 128x128, 8 warps (2m x 4n), warp tile m64n32, 2 CTAs/SM.
// R2 structure with BK=64 / STAGES=2: same 64KB smem, half the barriers.
#define BM 128
#define BN 128
#define BK 64
#define KTILES (IN_F / BK)   // 64
#define STAGES 2

#define A_STAGE_BYTES (BM * BK * 2)          // 16384
#define B_STAGE_BYTES (BN * BK * 2)          // 16384
#define STAGE_BYTES   (A_STAGE_BYTES + B_STAGE_BYTES)   // 32768
#define SMEM_TOTAL    (STAGES * STAGE_BYTES)            // 65536 (== R2)

// ---------------------------------------------------------------------------
// Device scratch (static — no cudaMalloc anywhere)
// ---------------------------------------------------------------------------
__device__ __half  g_q[(size_t)OUT_F * IN_F];    // ternary weights, fp16 exact
__device__ __half  g_xh[(size_t)TOKENS * IN_F];  // fp16(x)
__device__ double  g_partial[1024];
__device__ float   g_alpha;

// ---------------------------------------------------------------------------
// PTX helpers (baseline compute_103 — NO tcgen05/TMA-arch features)
// ---------------------------------------------------------------------------
__device__ __forceinline__ uint32_t smem_u32(const void* p) {
    uint32_t a;
    asm("{ .reg .u64 t; cvta.to.shared.u64 t, %1; cvt.u32.u64 %0, t; }"
        : "=r"(a) : "l"(p));
    return a;
}

__device__ __forceinline__ void cp_async16(uint32_t s, const void* g) {
    asm volatile(
        "{ .reg .u64 gg; cvta.to.global.u64 gg, %1; "
        "cp.async.cg.shared.global [%0], [gg], 16; }"
        :: "r"(s), "l"(g));
}
#define CP_COMMIT() asm volatile("cp.async.commit_group;" ::: "memory")
#define CP_WAIT(N)  asm volatile("cp.async.wait_group %0;" :: "n"(N) : "memory")

__device__ __forceinline__ void ldsm_x4(uint32_t& r0, uint32_t& r1,
                                        uint32_t& r2, uint32_t& r3, uint32_t a) {
    asm volatile("ldmatrix.sync.aligned.m8n8.x4.shared.b16 {%0,%1,%2,%3}, [%4];"
                 : "=r"(r0), "=r"(r1), "=r"(r2), "=r"(r3) : "r"(a));
}

__device__ __forceinline__ void mma16816(float& c0, float& c1, float& c2, float& c3,
                                         uint32_t a0, uint32_t a1, uint32_t a2, uint32_t a3,
                                         uint32_t b0, uint32_t b1) {
    asm volatile(
        "mma.sync.aligned.m16n8k16.row.col.f32.f16.f16.f32 "
        "{%0,%1,%2,%3}, {%4,%5,%6,%7}, {%8,%9}, {%0,%1,%2,%3};"
        : "+f"(c0), "+f"(c1), "+f"(c2), "+f"(c3)
        : "r"(a0), "r"(a1), "r"(a2), "r"(a3), "r"(b0), "r"(b1));
}

// SW128 swizzle for 128-byte rows: 16B chunk c (0..7), row r.
// byte = r*128 + ((c ^ (r&7)) << 4). ldmatrix phases read 8 consecutive rows
// at fixed c -> 8 distinct chunks -> all 32 banks, conflict-free.
__device__ __forceinline__ uint32_t swz128(uint32_t row, uint32_t c) {
    return row * 128u + ((c ^ (row & 7u)) << 4);
}

// ---------------------------------------------------------------------------
// Kernel 1: deterministic |W| partial sums (fp64 accumulators)
// ---------------------------------------------------------------------------
__global__ void reduce_abs_kernel(const float* __restrict__ w) {
    __shared__ double sh[256];
    const size_t n4 = (size_t)OUT_F * IN_F / 4;
    const float4* w4 = (const float4*)w;
    double acc = 0.0;
    for (size_t i = (size_t)blockIdx.x * 256 + threadIdx.x; i < n4;
         i += (size_t)1024 * 256) {
        float4 v = w4[i];
        acc += (double)fabsf(v.x) + (double)fabsf(v.y) +
               (double)fabsf(v.z) + (double)fabsf(v.w);
    }
    int tid = threadIdx.x;
    sh[tid] = acc;
    __syncthreads();
    for (int s = 128; s > 0; s >>= 1) {
        if (tid < s) sh[tid] += sh[tid + s];
        __syncthreads();
    }
    if (tid == 0) g_partial[blockIdx.x] = sh[0];
}

__global__ void finalize_alpha_kernel() {
    __shared__ double sh[256];
    int tid = threadIdx.x;
    double a = g_partial[tid] + g_partial[tid + 256] +
               g_partial[tid + 512] + g_partial[tid + 768];
    sh[tid] = a;
    __syncthreads();
    for (int s = 128; s > 0; s >>= 1) {
        if (tid < s) sh[tid] += sh[tid + s];
        __syncthreads();
    }
    if (tid == 0) g_alpha = (float)(sh[0] / ((double)OUT_F * (double)IN_F));
}

// ---------------------------------------------------------------------------
// Kernel 3: ternary quantize W -> fp16 {-1, 0, +1}
// ---------------------------------------------------------------------------
__global__ void quantize_kernel(const float* __restrict__ w) {
    const float a = g_alpha;
    size_t i = (size_t)blockIdx.x * blockDim.x + threadIdx.x;
    const size_t n4 = (size_t)OUT_F * IN_F / 4;
    if (i >= n4) return;
    float4 v = ((const float4*)w)[i];
    float q0 = (v.x > a) ? 1.0f : ((v.x < -a) ? -1.0f : 0.0f);
    float q1 = (v.y > a) ? 1.0f : ((v.y < -a) ? -1.0f : 0.0f);
    float q2 = (v.z > a) ? 1.0f : ((v.z < -a) ? -1.0f : 0.0f);
    float q3 = (v.w > a) ? 1.0f : ((v.w < -a) ? -1.0f : 0.0f);
    __half2* o = (__half2*)g_q;
    o[i * 2 + 0] = __half2(__float2half_rn(q0), __float2half_rn(q1));
    o[i * 2 + 1] = __half2(__float2half_rn(q2), __float2half_rn(q3));
}

// ---------------------------------------------------------------------------
// Kernel 4: x -> fp16
// ---------------------------------------------------------------------------
__global__ void convert_x_kernel(const float* __restrict__ x) {
    size_t i = (size_t)blockIdx.x * blockDim.x + threadIdx.x;
    const size_t n4 = (size_t)TOKENS * IN_F / 4;
    if (i >= n4) return;
    float4 v = ((const float4*)x)[i];
    __half2* o = (__half2*)g_xh;
    o[i * 2 + 0] = __half2(__float2half_rn(v.x), __float2half_rn(v.y));
    o[i * 2 + 1] = __half2(__float2half_rn(v.z), __float2half_rn(v.w));
}

// ---------------------------------------------------------------------------
// Kernel 5: fp16 HMMA GEMM (R2 shape). BK=64, ping-pong stages (same 64KB),
// ks loop not unrolled to keep fragment liveness (and regs) at R2 level.
// out[m, n] = (sum_k xh[m,k] * q[n,k]) * scale[n] + bias[n]
// ---------------------------------------------------------------------------
__device__ __forceinline__ void load_stage(uint32_t sbase, int k0,
                                           const __half* __restrict__ xrow,
                                           const __half* __restrict__ qrow,
                                           int tid) {
    // A: 128 rows x 8 chunks = 1024; B: same. 4+4 cp.async per thread.
#pragma unroll
    for (int j = 0; j < 4; j++) {
        int id = tid + j * 256;
        uint32_t row = (uint32_t)(id >> 3);
        uint32_t c = (uint32_t)(id & 7);
        cp_async16(sbase + swz128(row, c),
                   xrow + (size_t)row * IN_F + k0 + c * 8);
        cp_async16(sbase + A_STAGE_BYTES + swz128(row, c),
                   qrow + (size_t)row * IN_F + k0 + c * 8);
    }
}

__global__ void __launch_bounds__(256, 2)
gemm_kernel(float* __restrict__ out, const float* __restrict__ scale,
            const float* __restrict__ bias) {
    extern __shared__ char smem[];
    const uint32_t sb = smem_u32(smem);
    const int tid = threadIdx.x;
    const int lane = tid & 31;
    const int wid = tid >> 5;
    const int warp_m = (wid & 1) * 64;
    const int warp_n = (wid >> 1) * 32;

    const int m0 = blockIdx.x * BM;   // m fastest -> q n-tiles L2-shared
    const int n0 = blockIdx.y * BN;

    const __half* xrow = g_xh + (size_t)m0 * IN_F;
    const __half* qrow = g_q + (size_t)n0 * IN_F;

    // Base swizzled offsets at ks=0; per-ks address = base ^ (ks<<5)
    // (valid because the 16B-chunk index bits of ks are disjoint from the
    //  base chunk bit and XOR commutes with the swizzle).
    uint32_t offA[4], offB[2];
#pragma unroll
    for (int mt = 0; mt < 4; mt++)
        offA[mt] = swz128((uint32_t)(warp_m + mt * 16 + (lane & 15)),
                          (uint32_t)(lane >> 4));
#pragma unroll
    for (int ng = 0; ng < 2; ng++)
        offB[ng] = A_STAGE_BYTES +
                   swz128((uint32_t)(warp_n + ng * 16 + ((lane >> 4) << 3) + (lane & 7)),
                          (uint32_t)((lane >> 3) & 1));

    float acc[4][4][4];
#pragma unroll
    for (int mt = 0; mt < 4; mt++)
#pragma unroll
        for (int nt = 0; nt < 4; nt++)
#pragma unroll
            for (int j = 0; j < 4; j++) acc[mt][nt][j] = 0.0f;

    // Prologue: stage 0
    load_stage(sb, 0, xrow, qrow, tid);
    CP_COMMIT();

    for (int kt = 0; kt < KTILES; kt++) {
        CP_WAIT(0);
        __syncthreads();

        if (kt + 1 < KTILES)
            load_stage(sb + ((kt + 1) & 1) * STAGE_BYTES, (kt + 1) * BK,
                       xrow, qrow, tid);
        CP_COMMIT();

        const uint32_t stage = sb + (kt & 1) * STAGE_BYTES;

#pragma unroll 1
        for (int ks = 0; ks < 4; ks++) {
            const uint32_t kx = (uint32_t)(ks << 5);
            uint32_t af[4][4];
            uint32_t bf[4][2];
#pragma unroll
            for (int mt = 0; mt < 4; mt++)
                ldsm_x4(af[mt][0], af[mt][1], af[mt][2], af[mt][3],
                        stage + (offA[mt] ^ kx));
#pragma unroll
            for (int ng = 0; ng < 2; ng++) {
                uint32_t r0, r1, r2, r3;
                ldsm_x4(r0, r1, r2, r3, stage + (offB[ng] ^ kx));
                bf[2 * ng + 0][0] = r0; bf[2 * ng + 0][1] = r1;
                bf[2 * ng + 1][0] = r2; bf[2 * ng + 1][1] = r3;
            }
#pragma unroll
            for (int mt = 0; mt < 4; mt++)
#pragma unroll
                for (int nt = 0; nt < 4; nt++)
                    mma16816(acc[mt][nt][0], acc[mt][nt][1],
                             acc[mt][nt][2], acc[mt][nt][3],
                             af[mt][0], af[mt][1], af[mt][2], af[mt][3],
                             bf[nt][0], bf[nt][1]);
        }
    }

    // Epilogue: scale + bias, direct fp32 stores.
#pragma unroll
    for (int nt = 0; nt < 4; nt++) {
        const int c = n0 + warp_n + nt * 8 + (lane & 3) * 2;
        const float s0 = __ldg(scale + c), s1 = __ldg(scale + c + 1);
        const float b0 = __ldg(bias + c), b1 = __ldg(bias + c + 1);
#pragma unroll
        for (int mt = 0; mt < 4; mt++) {
            const int r0 = m0 + warp_m + mt * 16 + (lane >> 2);
            float2 v0 = {acc[mt][nt][0] * s0 + b0, acc[mt][nt][1] * s1 + b1};
            float2 v1 = {acc[mt][nt][2] * s0 + b0, acc[mt][nt][3] * s1 + b1};
            *(float2*)(out + (size_t)r0 * OUT_F + c) = v0;
            *(float2*)(out + (size_t)(r0 + 8) * OUT_F + c) = v1;
        }
    }
}

// ---------------------------------------------------------------------------
// kernel_launch
// ---------------------------------------------------------------------------
extern "C" void kernel_launch(void* const* d_in, const int* in_sizes, int n_in,
                              void* d_out, int out_size) {
    const float* x      = (const float*)d_in[0];  // (4096, 4096)
    const float* weight = (const float*)d_in[1];  // (11008, 4096)
    const float* scale  = (const float*)d_in[2];  // (11008, 1)
    const float* bias   = (const float*)d_in[3];  // (11008,)
    float* out = (float*)d_out;                   // (4096, 11008)
    (void)in_sizes; (void)n_in; (void)out_size;

    reduce_abs_kernel<<<1024, 256>>>(weight);
    finalize_alpha_kernel<<<1, 256>>>();
    quantize_kernel<<<(int)(((size_t)OUT_F * IN_F / 4 + 255) / 256), 256>>>(weight);
    convert_x_kernel<<<(int)(((size_t)TOKENS * IN_F / 4 + 255) / 256), 256>>>(x);

    cudaFuncSetAttribute(gemm_kernel,
                         cudaFuncAttributeMaxDynamicSharedMemorySize, SMEM_TOTAL);
    dim3 grid(TOKENS / BM, OUT_F / BN);  // (32, 86)
    gemm_kernel<<<grid, 256, SMEM_TOTAL>>>(out, scale, bias);
}

// round 12
// speedup vs baseline: 1.4579x; 1.0020x over previous
#include <cuda_runtime.h>
#include <cuda_fp16.h>
#include <cstdint>
#include <cstddef>

// ---------------------------------------------------------------------------
// Problem constants
// ---------------------------------------------------------------------------
#define TOKENS 4096   // M
#define IN_F   4096   // K
#define OUT_F  11008  // N

// GEMM tiling: CTA 128x128, 8 warps (2m x 4n), warp tile m64n32, 2 CTAs/SM.
// R9 structure (BK=64) with STAGES=3: distance-2 cp.async prefetch.
#define BM 128
#define BN 128
#define BK 64
#define KTILES (IN_F / BK)   // 64
#define STAGES 3

#define A_STAGE_BYTES (BM * BK * 2)          // 16384
#define B_STAGE_BYTES (BN * BK * 2)          // 16384
#define STAGE_BYTES   (A_STAGE_BYTES + B_STAGE_BYTES)   // 32768
#define SMEM_TOTAL    (STAGES * STAGE_BYTES)            // 98304 (2 CTAs = 192KB <= 228KB)

// ---------------------------------------------------------------------------
// Device scratch (static — no cudaMalloc anywhere)
// ---------------------------------------------------------------------------
__device__ __half  g_q[(size_t)OUT_F * IN_F];    // ternary weights, fp16 exact
__device__ __half  g_xh[(size_t)TOKENS * IN_F];  // fp16(x)
__device__ double  g_partial[1024];
__device__ float   g_alpha;

// ---------------------------------------------------------------------------
// PTX helpers (baseline compute_103 — NO tcgen05/TMA-arch features)
// ---------------------------------------------------------------------------
__device__ __forceinline__ uint32_t smem_u32(const void* p) {
    uint32_t a;
    asm("{ .reg .u64 t; cvta.to.shared.u64 t, %1; cvt.u32.u64 %0, t; }"
        : "=r"(a) : "l"(p));
    return a;
}

__device__ __forceinline__ void cp_async16(uint32_t s, const void* g) {
    asm volatile(
        "{ .reg .u64 gg; cvta.to.global.u64 gg, %1; "
        "cp.async.cg.shared.global [%0], [gg], 16; }"
        :: "r"(s), "l"(g));
}
#define CP_COMMIT() asm volatile("cp.async.commit_group;" ::: "memory")
#define CP_WAIT(N)  asm volatile("cp.async.wait_group %0;" :: "n"(N) : "memory")

__device__ __forceinline__ void ldsm_x4(uint32_t& r0, uint32_t& r1,
                                        uint32_t& r2, uint32_t& r3, uint32_t a) {
    asm volatile("ldmatrix.sync.aligned.m8n8.x4.shared.b16 {%0,%1,%2,%3}, [%4];"
                 : "=r"(r0), "=r"(r1), "=r"(r2), "=r"(r3) : "r"(a));
}

__device__ __forceinline__ void mma16816(float& c0, float& c1, float& c2, float& c3,
                                         uint32_t a0, uint32_t a1, uint32_t a2, uint32_t a3,
                                         uint32_t b0, uint32_t b1) {
    asm volatile(
        "mma.sync.aligned.m16n8k16.row.col.f32.f16.f16.f32 "
        "{%0,%1,%2,%3}, {%4,%5,%6,%7}, {%8,%9}, {%0,%1,%2,%3};"
        : "+f"(c0), "+f"(c1), "+f"(c2), "+f"(c3)
        : "r"(a0), "r"(a1), "r"(a2), "r"(a3), "r"(b0), "r"(b1));
}

// SW128 swizzle for 128-byte rows: 16B chunk c (0..7), row r.
// byte = r*128 + ((c ^ (r&7)) << 4). ldmatrix phases read 8 consecutive rows
// at fixed c -> 8 distinct chunks -> all 32 banks, conflict-free.
__device__ __forceinline__ uint32_t swz128(uint32_t row, uint32_t c) {
    return row * 128u + ((c ^ (row & 7u)) << 4);
}

// ---------------------------------------------------------------------------
// Kernel 1: deterministic |W| partial sums (fp64 accumulators)
// ---------------------------------------------------------------------------
__global__ void reduce_abs_kernel(const float* __restrict__ w) {
    __shared__ double sh[256];
    const size_t n4 = (size_t)OUT_F * IN_F / 4;
    const float4* w4 = (const float4*)w;
    double acc = 0.0;
    for (size_t i = (size_t)blockIdx.x * 256 + threadIdx.x; i < n4;
         i += (size_t)1024 * 256) {
        float4 v = w4[i];
        acc += (double)fabsf(v.x) + (double)fabsf(v.y) +
               (double)fabsf(v.z) + (double)fabsf(v.w);
    }
    int tid = threadIdx.x;
    sh[tid] = acc;
    __syncthreads();
    for (int s = 128; s > 0; s >>= 1) {
        if (tid < s) sh[tid] += sh[tid + s];
        __syncthreads();
    }
    if (tid == 0) g_partial[blockIdx.x] = sh[0];
}

__global__ void finalize_alpha_kernel() {
    __shared__ double sh[256];
    int tid = threadIdx.x;
    double a = g_partial[tid] + g_partial[tid + 256] +
               g_partial[tid + 512] + g_partial[tid + 768];
    sh[tid] = a;
    __syncthreads();
    for (int s = 128; s > 0; s >>= 1) {
        if (tid < s) sh[tid] += sh[tid + s];
        __syncthreads();
    }
    if (tid == 0) g_alpha = (float)(sh[0] / ((double)OUT_F * (double)IN_F));
}

// ---------------------------------------------------------------------------
// Kernel 3: ternary quantize W -> fp16 {-1, 0, +1}
// ---------------------------------------------------------------------------
__global__ void quantize_kernel(const float* __restrict__ w) {
    const float a = g_alpha;
    size_t i = (size_t)blockIdx.x * blockDim.x + threadIdx.x;
    const size_t n4 = (size_t)OUT_F * IN_F / 4;
    if (i >= n4) return;
    float4 v = ((const float4*)w)[i];
    float q0 = (v.x > a) ? 1.0f : ((v.x < -a) ? -1.0f : 0.0f);
    float q1 = (v.y > a) ? 1.0f : ((v.y < -a) ? -1.0f : 0.0f);
    float q2 = (v.z > a) ? 1.0f : ((v.z < -a) ? -1.0f : 0.0f);
    float q3 = (v.w > a) ? 1.0f : ((v.w < -a) ? -1.0f : 0.0f);
    __half2* o = (__half2*)g_q;
    o[i * 2 + 0] = __half2(__float2half_rn(q0), __float2half_rn(q1));
    o[i * 2 + 1] = __half2(__float2half_rn(q2), __float2half_rn(q3));
}

// ---------------------------------------------------------------------------
// Kernel 4: x -> fp16
// ---------------------------------------------------------------------------
__global__ void convert_x_kernel(const float* __restrict__ x) {
    size_t i = (size_t)blockIdx.x * blockDim.x + threadIdx.x;
    const size_t n4 = (size_t)TOKENS * IN_F / 4;
    if (i >= n4) return;
    float4 v = ((const float4*)x)[i];
    __half2* o = (__half2*)g_xh;
    o[i * 2 + 0] = __half2(__float2half_rn(v.x), __float2half_rn(v.y));
    o[i * 2 + 1] = __half2(__float2half_rn(v.z), __float2half_rn(v.w));
}

// ---------------------------------------------------------------------------
// Kernel 5: fp16 HMMA GEMM (R9 shape). BK=64, 3-stage ring, distance-2
// prefetch; ks loop not unrolled to keep register liveness at R2 level.
// out[m, n] = (sum_k xh[m,k] * q[n,k]) * scale[n] + bias[n]
// ---------------------------------------------------------------------------
__device__ __forceinline__ void load_stage(uint32_t sbase, int k0,
                                           const __half* __restrict__ xrow,
                                           const __half* __restrict__ qrow,
                                           int tid) {
    // A: 128 rows x 8 chunks = 1024; B: same. 4+4 cp.async per thread.
#pragma unroll
    for (int j = 0; j < 4; j++) {
        int id = tid + j * 256;
        uint32_t row = (uint32_t)(id >> 3);
        uint32_t c = (uint32_t)(id & 7);
        cp_async16(sbase + swz128(row, c),
                   xrow + (size_t)row * IN_F + k0 + c * 8);
        cp_async16(sbase + A_STAGE_BYTES + swz128(row, c),
                   qrow + (size_t)row * IN_F + k0 + c * 8);
    }
}

__global__ void __launch_bounds__(256, 2)
gemm_kernel(float* __restrict__ out, const float* __restrict__ scale,
            const float* __restrict__ bias) {
    extern __shared__ char smem[];
    const uint32_t sb = smem_u32(smem);
    const int tid = threadIdx.x;
    const int lane = tid & 31;
    const int wid = tid >> 5;
    const int warp_m = (wid & 1) * 64;
    const int warp_n = (wid >> 1) * 32;

    const int m0 = blockIdx.x * BM;   // m fastest -> q n-tiles L2-shared
    const int n0 = blockIdx.y * BN;

    const __half* xrow = g_xh + (size_t)m0 * IN_F;
    const __half* qrow = g_q + (size_t)n0 * IN_F;

    // Base swizzled offsets at ks=0; per-ks address = base ^ (ks<<5)
    // (chunk bits of ks are disjoint from the base chunk bit).
    uint32_t offA[4], offB[2];
#pragma unroll
    for (int mt = 0; mt < 4; mt++)
        offA[mt] = swz128((uint32_t)(warp_m + mt * 16 + (lane & 15)),
                          (uint32_t)(lane >> 4));
#pragma unroll
    for (int ng = 0; ng < 2; ng++)
        offB[ng] = A_STAGE_BYTES +
                   swz128((uint32_t)(warp_n + ng * 16 + ((lane >> 4) << 3) + (lane & 7)),
                          (uint32_t)((lane >> 3) & 1));

    float acc[4][4][4];
#pragma unroll
    for (int mt = 0; mt < 4; mt++)
#pragma unroll
        for (int nt = 0; nt < 4; nt++)
#pragma unroll
            for (int j = 0; j < 4; j++) acc[mt][nt][j] = 0.0f;

    // Prologue: stages 0..1
#pragma unroll
    for (int s = 0; s < STAGES - 1; s++) {
        load_stage(sb + s * STAGE_BYTES, s * BK, xrow, qrow, tid);
        CP_COMMIT();
    }

    int s_comp = 0, s_load = STAGES - 1;
    for (int kt = 0; kt < KTILES; kt++) {
        CP_WAIT(STAGES - 2);
        __syncthreads();

        int kn = kt + STAGES - 1;
        if (kn < KTILES)
            load_stage(sb + s_load * STAGE_BYTES, kn * BK, xrow, qrow, tid);
        CP_COMMIT();
        if (++s_load == STAGES) s_load = 0;

        const uint32_t stage = sb + s_comp * STAGE_BYTES;
        if (++s_comp == STAGES) s_comp = 0;

#pragma unroll 1
        for (int ks = 0; ks < 4; ks++) {
            const uint32_t kx = (uint32_t)(ks << 5);
            uint32_t af[4][4];
            uint32_t bf[4][2];
#pragma unroll
            for (int mt = 0; mt < 4; mt++)
                ldsm_x4(af[mt][0], af[mt][1], af[mt][2], af[mt][3],
                        stage + (offA[mt] ^ kx));
#pragma unroll
            for (int ng = 0; ng < 2; ng++) {
                uint32_t r0, r1, r2, r3;
                ldsm_x4(r0, r1, r2, r3, stage + (offB[ng] ^ kx));
                bf[2 * ng + 0][0] = r0; bf[2 * ng + 0][1] = r1;
                bf[2 * ng + 1][0] = r2; bf[2 * ng + 1][1] = r3;
            }
#pragma unroll
            for (int mt = 0; mt < 4; mt++)
#pragma unroll
                for (int nt = 0; nt < 4; nt++)
                    mma16816(acc[mt][nt][0], acc[mt][nt][1],
                             acc[mt][nt][2], acc[mt][nt][3],
                             af[mt][0], af[mt][1], af[mt][2], af[mt][3],
                             bf[nt][0], bf[nt][1]);
        }
    }

    // Epilogue: scale + bias, direct fp32 stores.
#pragma unroll
    for (int nt = 0; nt < 4; nt++) {
        const int c = n0 + warp_n + nt * 8 + (lane & 3) * 2;
        const float s0 = __ldg(scale + c), s1 = __ldg(scale + c + 1);
        const float b0 = __ldg(bias + c), b1 = __ldg(bias + c + 1);
#pragma unroll
        for (int mt = 0; mt < 4; mt++) {
            const int r0 = m0 + warp_m + mt * 16 + (lane >> 2);
            float2 v0 = {acc[mt][nt][0] * s0 + b0, acc[mt][nt][1] * s1 + b1};
            float2 v1 = {acc[mt][nt][2] * s0 + b0, acc[mt][nt][3] * s1 + b1};
            *(float2*)(out + (size_t)r0 * OUT_F + c) = v0;
            *(float2*)(out + (size_t)(r0 + 8) * OUT_F + c) = v1;
        }
    }
}

// ---------------------------------------------------------------------------
// kernel_launch
// ---------------------------------------------------------------------------
extern "C" void kernel_launch(void* const* d_in, const int* in_sizes, int n_in,
                              void* d_out, int out_size) {
    const float* x      = (const float*)d_in[0];  // (4096, 4096)
    const float* weight = (const float*)d_in[1];  // (11008, 4096)
    const float* scale  = (const float*)d_in[2];  // (11008, 1)
    const float* bias   = (const float*)d_in[3];  // (11008,)
    float* out = (float*)d_out;                   // (4096, 11008)
    (void)in_sizes; (void)n_in; (void)out_size;

    reduce_abs_kernel<<<1024, 256>>>(weight);
    finalize_alpha_kernel<<<1, 256>>>();
    quantize_kernel<<<(int)(((size_t)OUT_F * IN_F / 4 + 255) / 256), 256>>>(weight);
    convert_x_kernel<<<(int)(((size_t)TOKENS * IN_F / 4 + 255) / 256), 256>>>(x);

    cudaFuncSetAttribute(gemm_kernel,
                         cudaFuncAttributeMaxDynamicSharedMemorySize, SMEM_TOTAL);
    dim3 grid(TOKENS / BM, OUT_F / BN);  // (32, 86)
    gemm_kernel<<<grid, 256, SMEM_TOTAL>>>(out, scale, bias);
}

// round 13
// speedup vs baseline: 1.5496x; 1.0629x over previous
#include <cuda_runtime.h>
#include <cuda_fp16.h>
#include <cstdint>
#include <cstddef>

// ---------------------------------------------------------------------------
// Problem constants
// ---------------------------------------------------------------------------
#define TOKENS 4096   // M
#define IN_F   4096   // K
#define OUT_F  11008  // N

// GEMM tiling: CTA 128x128, 8 warps (2m x 4n), warp tile m64n32, 2 CTAs/SM.
// R10 structure; loads via single-thread cp.async.bulk from PRE-SWIZZLED
// tiled gmem (g_xh/g_q stored as 16KB smem-image tiles).
#define BM 128
#define BN 128
#define BK 64
#define KTILES (IN_F / BK)   // 64
#define STAGES 3

#define A_TILE_BYTES 16384                    // 128 rows x 128 B
#define B_TILE_BYTES 16384
#define STAGE_BYTES  (A_TILE_BYTES + B_TILE_BYTES)      // 32768
#define SMEM_TOTAL   (STAGES * STAGE_BYTES)             // 98304

// ---------------------------------------------------------------------------
// Device scratch (static — no cudaMalloc anywhere)
// Tiled layout: [row_block][kt][16KB tile], tile = swizzled smem image.
// ---------------------------------------------------------------------------
__device__ __half  g_q[(size_t)OUT_F * IN_F];    // ternary weights, tiled+swizzled
__device__ __half  g_xh[(size_t)TOKENS * IN_F];  // fp16(x), tiled+swizzled
__device__ double  g_partial[1024];
__device__ float   g_alpha;

// ---------------------------------------------------------------------------
// PTX helpers (baseline compute_103 — NO tcgen05/arch-'a' features;
// cp.async.bulk + mbarrier are plain sm_90 PTX)
// ---------------------------------------------------------------------------
__device__ __forceinline__ uint32_t smem_u32(const void* p) {
    uint32_t a;
    asm("{ .reg .u64 t; cvta.to.shared.u64 t, %1; cvt.u32.u64 %0, t; }"
        : "=r"(a) : "l"(p));
    return a;
}

__device__ __forceinline__ void bulk_cp(uint32_t dst, const void* src,
                                        uint32_t bytes, uint32_t mbar) {
    asm volatile(
        "{ .reg .u64 g; cvta.to.global.u64 g, %1; "
        "cp.async.bulk.shared::cta.global.mbarrier::complete_tx::bytes "
        "[%0], [g], %2, [%3]; }"
        :: "r"(dst), "l"(src), "r"(bytes), "r"(mbar) : "memory");
}

#define MBAR_INIT(a, c) \
    asm volatile("mbarrier.init.shared.b64 [%0], %1;" :: "r"(a), "r"((uint32_t)(c)) : "memory")
#define MBAR_EXPECT_TX(a, b) \
    asm volatile("mbarrier.arrive.expect_tx.shared.b64 _, [%0], %1;" \
                 :: "r"(a), "r"((uint32_t)(b)) : "memory")
#define FENCE_PROXY_ASYNC() \
    asm volatile("fence.proxy.async.shared::cta;" ::: "memory")

__device__ __forceinline__ void mbar_wait(uint32_t addr, uint32_t parity) {
    asm volatile(
        "{\n\t"
        ".reg .pred P;\n\t"
        "WL_%=:\n\t"
        "mbarrier.try_wait.parity.acquire.cta.shared::cta.b64 P, [%0], %1, 0x989680;\n\t"
        "@P bra WD_%=;\n\t"
        "bra WL_%=;\n\t"
        "WD_%=:\n\t"
        "}"
        :: "r"(addr), "r"(parity) : "memory");
}

__device__ __forceinline__ void ldsm_x4(uint32_t& r0, uint32_t& r1,
                                        uint32_t& r2, uint32_t& r3, uint32_t a) {
    asm volatile("ldmatrix.sync.aligned.m8n8.x4.shared.b16 {%0,%1,%2,%3}, [%4];"
                 : "=r"(r0), "=r"(r1), "=r"(r2), "=r"(r3) : "r"(a));
}

__device__ __forceinline__ void mma16816(float& c0, float& c1, float& c2, float& c3,
                                         uint32_t a0, uint32_t a1, uint32_t a2, uint32_t a3,
                                         uint32_t b0, uint32_t b1) {
    asm volatile(
        "mma.sync.aligned.m16n8k16.row.col.f32.f16.f16.f32 "
        "{%0,%1,%2,%3}, {%4,%5,%6,%7}, {%8,%9}, {%0,%1,%2,%3};"
        : "+f"(c0), "+f"(c1), "+f"(c2), "+f"(c3)
        : "r"(a0), "r"(a1), "r"(a2), "r"(a3), "r"(b0), "r"(b1));
}

// SW128 swizzle for 128-byte rows: 16B chunk c (0..7), row r.
__device__ __forceinline__ uint32_t swz128(uint32_t row, uint32_t c) {
    return row * 128u + ((c ^ (row & 7u)) << 4);
}

// ---------------------------------------------------------------------------
// Kernel 1: deterministic |W| partial sums (fp64 accumulators)
// ---------------------------------------------------------------------------
__global__ void reduce_abs_kernel(const float* __restrict__ w) {
    __shared__ double sh[256];
    const size_t n4 = (size_t)OUT_F * IN_F / 4;
    const float4* w4 = (const float4*)w;
    double acc = 0.0;
    for (size_t i = (size_t)blockIdx.x * 256 + threadIdx.x; i < n4;
         i += (size_t)1024 * 256) {
        float4 v = w4[i];
        acc += (double)fabsf(v.x) + (double)fabsf(v.y) +
               (double)fabsf(v.z) + (double)fabsf(v.w);
    }
    int tid = threadIdx.x;
    sh[tid] = acc;
    __syncthreads();
    for (int s = 128; s > 0; s >>= 1) {
        if (tid < s) sh[tid] += sh[tid + s];
        __syncthreads();
    }
    if (tid == 0) g_partial[blockIdx.x] = sh[0];
}

__global__ void finalize_alpha_kernel() {
    __shared__ double sh[256];
    int tid = threadIdx.x;
    double a = g_partial[tid] + g_partial[tid + 256] +
               g_partial[tid + 512] + g_partial[tid + 768];
    sh[tid] = a;
    __syncthreads();
    for (int s = 128; s > 0; s >>= 1) {
        if (tid < s) sh[tid] += sh[tid + s];
        __syncthreads();
    }
    if (tid == 0) g_alpha = (float)(sh[0] / ((double)OUT_F * (double)IN_F));
}

// ---------------------------------------------------------------------------
// Kernel 3: ternary quantize W -> fp16 tiles, pre-swizzled smem image.
// One thread per 16B chunk (8 weights).
// ---------------------------------------------------------------------------
__global__ void quantize_kernel(const float* __restrict__ w) {
    const float a = g_alpha;
    uint32_t id = blockIdx.x * 256 + threadIdx.x;   // < 86*65536
    uint32_t nb = id >> 16;           // 128-row block (0..85)
    uint32_t t = id & 65535;
    uint32_t kt = t >> 10;            // k chunk (0..63)
    uint32_t wv = t & 1023;
    uint32_t r = wv >> 3;             // row in tile (0..127)
    uint32_t c = wv & 7;              // 16B chunk in row (0..7)
    const float* src = w + ((size_t)(nb * 128 + r)) * IN_F + kt * 64 + c * 8;
    float4 v0 = *(const float4*)src;
    float4 v1 = *(const float4*)(src + 4);
    __half h[8];
    h[0] = __float2half_rn((v0.x > a) ? 1.0f : ((v0.x < -a) ? -1.0f : 0.0f));
    h[1] = __float2half_rn((v0.y > a) ? 1.0f : ((v0.y < -a) ? -1.0f : 0.0f));
    h[2] = __float2half_rn((v0.z > a) ? 1.0f : ((v0.z < -a) ? -1.0f : 0.0f));
    h[3] = __float2half_rn((v0.w > a) ? 1.0f : ((v0.w < -a) ? -1.0f : 0.0f));
    h[4] = __float2half_rn((v1.x > a) ? 1.0f : ((v1.x < -a) ? -1.0f : 0.0f));
    h[5] = __float2half_rn((v1.y > a) ? 1.0f : ((v1.y < -a) ? -1.0f : 0.0f));
    h[6] = __float2half_rn((v1.z > a) ? 1.0f : ((v1.z < -a) ? -1.0f : 0.0f));
    h[7] = __float2half_rn((v1.w > a) ? 1.0f : ((v1.w < -a) ? -1.0f : 0.0f));
    char* dst = (char*)g_q + (((size_t)nb * KTILES + kt) << 14) + swz128(r, c);
    *(uint4*)dst = *(const uint4*)h;
}

// ---------------------------------------------------------------------------
// Kernel 4: x -> fp16 tiles, pre-swizzled smem image.
// ---------------------------------------------------------------------------
__global__ void convert_x_kernel(const float* __restrict__ x) {
    uint32_t id = blockIdx.x * 256 + threadIdx.x;   // < 32*65536
    uint32_t mb = id >> 16;
    uint32_t t = id & 65535;
    uint32_t kt = t >> 10;
    uint32_t wv = t & 1023;
    uint32_t r = wv >> 3;
    uint32_t c = wv & 7;
    const float* src = x + ((size_t)(mb * 128 + r)) * IN_F + kt * 64 + c * 8;
    float4 v0 = *(const float4*)src;
    float4 v1 = *(const float4*)(src + 4);
    __half h[8];
    h[0] = __float2half_rn(v0.x); h[1] = __float2half_rn(v0.y);
    h[2] = __float2half_rn(v0.z); h[3] = __float2half_rn(v0.w);
    h[4] = __float2half_rn(v1.x); h[5] = __float2half_rn(v1.y);
    h[6] = __float2half_rn(v1.z); h[7] = __float2half_rn(v1.w);
    char* dst = (char*)g_xh + (((size_t)mb * KTILES + kt) << 14) + swz128(r, c);
    *(uint4*)dst = *(const uint4*)h;
}

// ---------------------------------------------------------------------------
// Kernel 5: fp16 HMMA GEMM (R10 mainloop). Loads: single-thread
// cp.async.bulk of pre-swizzled 16KB tiles, mbarrier completion.
// out[m, n] = (sum_k xh[m,k] * q[n,k]) * scale[n] + bias[n]
// ---------------------------------------------------------------------------
__global__ void __launch_bounds__(256, 2)
gemm_kernel(float* __restrict__ out, const float* __restrict__ scale,
            const float* __restrict__ bias) {
    extern __shared__ __align__(128) char smem[];
    __shared__ __align__(8) uint64_t mbar_s[STAGES];
    const uint32_t sb = smem_u32(smem);
    uint32_t mb[STAGES];
#pragma unroll
    for (int s = 0; s < STAGES; s++) mb[s] = smem_u32(&mbar_s[s]);

    const int tid = threadIdx.x;
    const int lane = tid & 31;
    const int wid = tid >> 5;
    const int warp_m = (wid & 1) * 64;
    const int warp_n = (wid >> 1) * 32;

    const int m0 = blockIdx.x * BM;   // m fastest -> q n-tiles L2-shared
    const int n0 = blockIdx.y * BN;

    const char* aT = (const char*)g_xh + ((size_t)blockIdx.x * KTILES << 14);
    const char* bT = (const char*)g_q + ((size_t)blockIdx.y * KTILES << 14);

    // ldsm swizzled offsets at ks=0; per-ks address = base ^ (ks<<5).
    uint32_t offA[4], offB[2];
#pragma unroll
    for (int mt = 0; mt < 4; mt++)
        offA[mt] = swz128((uint32_t)(warp_m + mt * 16 + (lane & 15)),
                          (uint32_t)(lane >> 4));
#pragma unroll
    for (int ng = 0; ng < 2; ng++)
        offB[ng] = A_TILE_BYTES +
                   swz128((uint32_t)(warp_n + ng * 16 + ((lane >> 4) << 3) + (lane & 7)),
                          (uint32_t)((lane >> 3) & 1));

    float acc[4][4][4];
#pragma unroll
    for (int mt = 0; mt < 4; mt++)
#pragma unroll
        for (int nt = 0; nt < 4; nt++)
#pragma unroll
            for (int j = 0; j < 4; j++) acc[mt][nt][j] = 0.0f;

    if (tid == 0) {
#pragma unroll
        for (int s = 0; s < STAGES; s++) MBAR_INIT(mb[s], 1);
    }
    __syncthreads();

    // Prologue: stages 0..1 <- chunks 0..1
    if (tid == 0) {
        FENCE_PROXY_ASYNC();
#pragma unroll
        for (int s = 0; s < STAGES - 1; s++) {
            MBAR_EXPECT_TX(mb[s], STAGE_BYTES);
            bulk_cp(sb + s * STAGE_BYTES, aT + ((size_t)s << 14),
                    A_TILE_BYTES, mb[s]);
            bulk_cp(sb + s * STAGE_BYTES + A_TILE_BYTES, bT + ((size_t)s << 14),
                    B_TILE_BYTES, mb[s]);
        }
    }

    int s_comp = 0, s_load = STAGES - 1;
    uint32_t phase = 0;
    for (int kt = 0; kt < KTILES; kt++) {
        __syncthreads();   // all warps done reading stage s_load (from kt-1)

        if (tid == 0 && kt + 2 < KTILES) {
            FENCE_PROXY_ASYNC();
            MBAR_EXPECT_TX(mb[s_load], STAGE_BYTES);
            bulk_cp(sb + s_load * STAGE_BYTES, aT + ((size_t)(kt + 2) << 14),
                    A_TILE_BYTES, mb[s_load]);
            bulk_cp(sb + s_load * STAGE_BYTES + A_TILE_BYTES,
                    bT + ((size_t)(kt + 2) << 14), B_TILE_BYTES, mb[s_load]);
        }
        if (++s_load == STAGES) s_load = 0;

        mbar_wait(mb[s_comp], phase);

        const uint32_t stage = sb + s_comp * STAGE_BYTES;
        if (++s_comp == STAGES) { s_comp = 0; phase ^= 1; }

#pragma unroll 1
        for (int ks = 0; ks < 4; ks++) {
            const uint32_t kx = (uint32_t)(ks << 5);
            uint32_t af[4][4];
            uint32_t bf[4][2];
#pragma unroll
            for (int mt = 0; mt < 4; mt++)
                ldsm_x4(af[mt][0], af[mt][1], af[mt][2], af[mt][3],
                        stage + (offA[mt] ^ kx));
#pragma unroll
            for (int ng = 0; ng < 2; ng++) {
                uint32_t r0, r1, r2, r3;
                ldsm_x4(r0, r1, r2, r3, stage + (offB[ng] ^ kx));
                bf[2 * ng + 0][0] = r0; bf[2 * ng + 0][1] = r1;
                bf[2 * ng + 1][0] = r2; bf[2 * ng + 1][1] = r3;
            }
#pragma unroll
            for (int mt = 0; mt < 4; mt++)
#pragma unroll
                for (int nt = 0; nt < 4; nt++)
                    mma16816(acc[mt][nt][0], acc[mt][nt][1],
                             acc[mt][nt][2], acc[mt][nt][3],
                             af[mt][0], af[mt][1], af[mt][2], af[mt][3],
                             bf[nt][0], bf[nt][1]);
        }
    }

    // Epilogue: scale + bias, direct fp32 stores.
#pragma unroll
    for (int nt = 0; nt < 4; nt++) {
        const int c = n0 + warp_n + nt * 8 + (lane & 3) * 2;
        const float s0 = __ldg(scale + c), s1 = __ldg(scale + c + 1);
        const float b0 = __ldg(bias + c), b1 = __ldg(bias + c + 1);
#pragma unroll
        for (int mt = 0; mt < 4; mt++) {
            const int r0 = m0 + warp_m + mt * 16 + (lane >> 2);
            float2 v0 = {acc[mt][nt][0] * s0 + b0, acc[mt][nt][1] * s1 + b1};
            float2 v1 = {acc[mt][nt][2] * s0 + b0, acc[mt][nt][3] * s1 + b1};
            *(float2*)(out + (size_t)r0 * OUT_F + c) = v0;
            *(float2*)(out + (size_t)(r0 + 8) * OUT_F + c) = v1;
        }
    }
}

// ---------------------------------------------------------------------------
// kernel_launch
// ---------------------------------------------------------------------------
extern "C" void kernel_launch(void* const* d_in, const int* in_sizes, int n_in,
                              void* d_out, int out_size) {
    const float* x      = (const float*)d_in[0];  // (4096, 4096)
    const float* weight = (const float*)d_in[1];  // (11008, 4096)
    const float* scale  = (const float*)d_in[2];  // (11008, 1)
    const float* bias   = (const float*)d_in[3];  // (11008,)
    float* out = (float*)d_out;                   // (4096, 11008)
    (void)in_sizes; (void)n_in; (void)out_size;

    reduce_abs_kernel<<<1024, 256>>>(weight);
    finalize_alpha_kernel<<<1, 256>>>();
    quantize_kernel<<<(OUT_F / 128) * 256, 256>>>(weight);   // 86*65536 chunks
    convert_x_kernel<<<(TOKENS / 128) * 256, 256>>>(x);      // 32*65536 chunks

    cudaFuncSetAttribute(gemm_kernel,
                         cudaFuncAttributeMaxDynamicSharedMemorySize, SMEM_TOTAL);
    dim3 grid(TOKENS / BM, OUT_F / BN);  // (32, 86)
    gemm_kernel<<<grid, 256, SMEM_TOTAL>>>(out, scale, bias);
}